// round 15
// baseline (speedup 1.0000x reference)
#include <cuda_runtime.h>
#include <math.h>

#define NPTS   2048
#define NB     16
#define NCHUNK 32         // n-dimension split per batch
#define TPB    256
#define MB     8          // m-points per thread (TPB*MB = NPTS)
#define NLOC   (NPTS / NCHUNK)          // 64 n-points per block
#define NBLK   (NB * NCHUNK)            // 512 blocks -> ~3.5/SM, one wave
#define NSUM   (NB * NCHUNK)            // 512 s-sum slots

// All zero-initialized at module load; every replay leaves them re-armed to 0.
__device__ unsigned g_min[NB * NPTS];   // per-(b,m) running min, order-REVERSED keys
__device__ float    g_ssum[NSUM];       // per-(b,nc) partial sums of |p|^2
__device__ float    g_bsum[NB];         // per-batch totals (min + ssum)
__device__ unsigned g_cnt_b[NB];        // per-batch arrival counters
__device__ unsigned g_count = 0;        // final arrival counter

// ---- order-REVERSING float<->uint keys: min(float) == max(key), identity = 0 ----
__device__ __forceinline__ unsigned fencMax(float f) {
    unsigned u = __float_as_uint(f);
    return (u & 0x80000000u) ? u : (~u & 0x7FFFFFFFu);
}
__device__ __forceinline__ float fdecMax(unsigned k) {
    unsigned u = (k & 0x80000000u) ? k : (~k & 0x7FFFFFFFu);
    return __uint_as_float(u);
}

__device__ __forceinline__ void quat2mat(const float q[4], float R[3][3]) {
    float w = q[0], x = q[1], y = q[2], z = q[3];
    R[0][0] = 1.f - 2.f * (y * y + z * z);
    R[0][1] = 2.f * (x * y - w * z);
    R[0][2] = 2.f * (x * z + w * y);
    R[1][0] = 2.f * (x * y + w * z);
    R[1][1] = 1.f - 2.f * (x * x + z * z);
    R[1][2] = 2.f * (y * z - w * x);
    R[2][0] = 2.f * (x * z - w * y);
    R[2][1] = 2.f * (y * z + w * x);
    R[2][2] = 1.f - 2.f * (x * x + y * y);
}

// Single fused kernel. grid = 16 batches x 32 n-chunks, 256 threads.
__global__ __launch_bounds__(TPB, 4) void fused_kernel(const float* __restrict__ pq,
                                                       const float* __restrict__ gq,
                                                       const float* __restrict__ points,
                                                       float* __restrict__ out) {
    __shared__ float4 smN[NLOC + 1];    // (r0, r1, r2, s) per n-point; +1 prefetch pad
    __shared__ float  sA[9];
    __shared__ float  red[TPB / 32];
    __shared__ bool   isBatchLast, isFinal;

    const int b   = blockIdx.x >> 5;                  // batch
    const int nc  = blockIdx.x & (NCHUNK - 1);        // n-chunk
    const int tid = threadIdx.x;
    const float* __restrict__ P = points + b * 3 * NPTS;

    // ---- per-block quaternion math: A = Rp^T * Rg for this batch ----
    if (tid == 0) {
        float p[4], g[4];
#pragma unroll
        for (int i = 0; i < 4; i++) { p[i] = pq[b * 4 + i]; g[i] = gq[b * 4 + i]; }
        float np2 = 0.f, ng2 = 0.f;
#pragma unroll
        for (int i = 0; i < 4; i++) { np2 += p[i] * p[i]; ng2 += g[i] * g[i]; }
        float ip = 1.f / fmaxf(sqrtf(np2), 1e-8f);
        float ig = 1.f / fmaxf(sqrtf(ng2), 1e-8f);
#pragma unroll
        for (int i = 0; i < 4; i++) { p[i] *= ip; g[i] *= ig; }
        float Rp[3][3], Rg[3][3];
        quat2mat(p, Rp);
        quat2mat(g, Rg);
#pragma unroll
        for (int i = 0; i < 3; i++)
#pragma unroll
            for (int j = 0; j < 3; j++) {
                float a = 0.f;
#pragma unroll
                for (int k = 0; k < 3; k++) a += Rp[k][i] * Rg[k][j];
                sA[i * 3 + j] = a;
            }
    }

    // ---- cos_loss: block 0, warp 0 (lanes 0..15 own one batch each) ----
    if (blockIdx.x == 0 && tid < 32) {
        float cos_term = 0.f;
        if (tid < NB) {
            float p[4], g[4];
#pragma unroll
            for (int i = 0; i < 4; i++) { p[i] = pq[tid * 4 + i]; g[i] = gq[tid * 4 + i]; }
            float dot = 0.f, np2 = 0.f, ng2 = 0.f;
#pragma unroll
            for (int i = 0; i < 4; i++) {
                dot += p[i] * g[i]; np2 += p[i] * p[i]; ng2 += g[i] * g[i];
            }
            cos_term = 1.f - dot / fmaxf(sqrtf(np2) * sqrtf(ng2), 1e-8f);
        }
#pragma unroll
        for (int o = 16; o > 0; o >>= 1) cos_term += __shfl_down_sync(0xFFFFFFFFu, cos_term, o);
        if (tid == 0) out[0] = cos_term * (1.f / (float)NB);
    }
    __syncthreads();

    const float A00 = sA[0], A01 = sA[1], A02 = sA[2];
    const float A10 = sA[3], A11 = sA[4], A12 = sA[5];
    const float A20 = sA[6], A21 = sA[7], A22 = sA[8];

    // ---- Phase 1: r/s table for this block's 64 n-points + chunk s-sum ----
    if (tid < NLOC) {
        int n = nc * NLOC + tid;
        float x = P[n], y = P[NPTS + n], z = P[2 * NPTS + n];
        float r0 = fmaf(A00, x, fmaf(A01, y, A02 * z));
        float r1 = fmaf(A10, x, fmaf(A11, y, A12 * z));
        float r2 = fmaf(A20, x, fmaf(A21, y, A22 * z));
        float s  = fmaf(x, x, fmaf(y, y, z * z));
        smN[tid] = make_float4(r0, r1, r2, s);

        float t = s;
#pragma unroll
        for (int o = 16; o > 0; o >>= 1) t += __shfl_down_sync(0xFFFFFFFFu, t, o);
        if ((tid & 31) == 0) red[tid >> 5] = t;
    }
    __syncthreads();
    if (tid == 0) {
        float t = 0.f;
#pragma unroll
        for (int w = 0; w < NLOC / 32; w++) t += red[w];
        g_ssum[blockIdx.x] = t;
    }

    // ---- Phase 2: each thread owns m = k*256 + tid, k in [0,8) ----
    float u0[MB], u1[MB], u2[MB];
#pragma unroll
    for (int k = 0; k < MB; k++) {
        int m = k * TPB + tid;
        u0[k] = -2.f * P[m];
        u1[k] = -2.f * P[NPTS + m];
        u2[k] = -2.f * P[2 * NPTS + m];
    }

    float mn[MB];
#pragma unroll
    for (int k = 0; k < MB; k++) mn[k] = INFINITY;

    // Software-pipelined scan over the 64 n-points: prefetch j+1 while
    // computing j (24 FFMA + 8 FMNMX of independent work hides the LDS).
    float4 t = smN[0];
#pragma unroll 4
    for (int j = 0; j < NLOC; j++) {
        float4 tn = smN[j + 1];            // pad entry read at j==NLOC-1 (unused)
#pragma unroll
        for (int k = 0; k < MB; k++) {
            float v = fmaf(u2[k], t.z, t.w);   // s - 2*r2*z
            v = fmaf(u1[k], t.y, v);           //   - 2*r1*y
            v = fmaf(u0[k], t.x, v);           //   - 2*r0*x
            mn[k] = fminf(mn[k], v);
        }
        t = tn;
    }

#pragma unroll
    for (int k = 0; k < MB; k++) {
        // min over floats == max over reversed keys; identity 0 == untouched slot
        atomicMax(&g_min[b * NPTS + k * TPB + tid], fencMax(mn[k]));
    }

    // ---- hierarchical finish: per-batch last block reduces its batch ----
    __threadfence();
    if (tid == 0) {
        unsigned prev = atomicAdd(&g_cnt_b[b], 1u);
        isBatchLast = (prev == NCHUNK - 1);
    }
    __syncthreads();
    if (!isBatchLast) return;

    __threadfence();  // all chunks of batch b are visible

    // 256 threads x 2 uint4 = 2048 mins of this batch; read, decode, re-arm.
    {
        uint4* gm = (uint4*)(g_min + b * NPTS);
        float acc = 0.f;
#pragma unroll
        for (int q = 0; q < 2; q++) {
            int idx = q * TPB + tid;
            uint4 v = gm[idx];
            acc += fdecMax(v.x) + fdecMax(v.y) + fdecMax(v.z) + fdecMax(v.w);
            gm[idx] = make_uint4(0u, 0u, 0u, 0u);
        }
        if (tid < NCHUNK) acc += g_ssum[b * NCHUNK + tid];

#pragma unroll
        for (int o = 16; o > 0; o >>= 1) acc += __shfl_down_sync(0xFFFFFFFFu, acc, o);
        if ((tid & 31) == 0) red[tid >> 5] = acc;
        __syncthreads();
        if (tid < 32) {
            acc = (tid < (TPB / 32)) ? red[tid] : 0.f;
#pragma unroll
            for (int o = 16; o > 0; o >>= 1) acc += __shfl_down_sync(0xFFFFFFFFu, acc, o);
            if (tid == 0) {
                g_bsum[b] = acc;
                g_cnt_b[b] = 0;              // re-arm per-batch counter
            }
        }
    }

    // ---- final: last batch-finisher sums the 16 batch totals ----
    __threadfence();
    if (tid == 0) {
        unsigned prev = atomicAdd(&g_count, 1u);
        isFinal = (prev == NB - 1);
    }
    __syncthreads();
    if (!isFinal) return;

    __threadfence();  // all g_bsum visible
    if (tid == 0) {
        float s = 0.f;
#pragma unroll
        for (int i = 0; i < NB; i++) s += g_bsum[i];   // fixed order -> deterministic
        float pt = s * (1.f / ((float)NB * (float)NPTS));
        if (isnan(pt)) pt = 0.f;
        out[1] = pt;
        g_count = 0;                        // re-arm final counter
    }
}

extern "C" void kernel_launch(void* const* d_in, const int* in_sizes, int n_in,
                              void* d_out, int out_size) {
    const float* pq  = (const float*)d_in[0];  // predquat (16,4)
    const float* gq  = (const float*)d_in[1];  // gtquat   (16,4)
    const float* pts = (const float*)d_in[2];  // points   (16,3,2048)
    float* out = (float*)d_out;                // [cos_loss, pt_loss]

    fused_kernel<<<NBLK, TPB>>>(pq, gq, pts, out);
}

// round 16
// speedup vs baseline: 1.0949x; 1.0949x over previous
#include <cuda_runtime.h>
#include <math.h>

#define NPTS   2048
#define NB     16
#define NCHUNK 32         // n-dimension split per batch
#define TPB    512
#define MB     4          // m-points per thread (TPB*MB = NPTS)
#define NLOC   (NPTS / NCHUNK)          // 64 n-points per block
#define NBLK   (NB * NCHUNK)            // 512 blocks -> 3+/SM resident
#define NSUM   (NB * NCHUNK)            // 512 s-sum slots

// All zero-initialized at module load; every replay leaves them re-armed to 0.
__device__ unsigned g_min[NB * NPTS];   // per-(b,m) running min, order-REVERSED keys
__device__ float    g_ssum[NSUM];       // per-(b,nc) partial sums of |p|^2
__device__ float    g_bsum[NB];         // per-batch totals (min + ssum)
__device__ unsigned g_cnt_b[NB];        // per-batch arrival counters
__device__ unsigned g_count = 0;        // final arrival counter

// ---- order-REVERSING float<->uint keys: min(float) == max(key), identity = 0 ----
__device__ __forceinline__ unsigned fencMax(float f) {
    unsigned u = __float_as_uint(f);
    return (u & 0x80000000u) ? u : (~u & 0x7FFFFFFFu);
}
__device__ __forceinline__ float fdecMax(unsigned k) {
    unsigned u = (k & 0x80000000u) ? k : (~k & 0x7FFFFFFFu);
    return __uint_as_float(u);
}

__device__ __forceinline__ void quat2mat(const float q[4], float R[3][3]) {
    float w = q[0], x = q[1], y = q[2], z = q[3];
    R[0][0] = 1.f - 2.f * (y * y + z * z);
    R[0][1] = 2.f * (x * y - w * z);
    R[0][2] = 2.f * (x * z + w * y);
    R[1][0] = 2.f * (x * y + w * z);
    R[1][1] = 1.f - 2.f * (x * x + z * z);
    R[1][2] = 2.f * (y * z - w * x);
    R[2][0] = 2.f * (x * z - w * y);
    R[2][1] = 2.f * (y * z + w * x);
    R[2][2] = 1.f - 2.f * (x * x + y * y);
}

// Single fused kernel. grid = 16 batches x 32 n-chunks, 512 threads.
__global__ __launch_bounds__(TPB, 3) void fused_kernel(const float* __restrict__ pq,
                                                       const float* __restrict__ gq,
                                                       const float* __restrict__ points,
                                                       float* __restrict__ out) {
    __shared__ float4 smN[NLOC];        // (r0, r1, r2, s) per n-point
    __shared__ float  sA[9];
    __shared__ float  red[TPB / 32];
    __shared__ bool   isBatchLast, isFinal;

    const int b   = blockIdx.x >> 5;                  // batch
    const int nc  = blockIdx.x & (NCHUNK - 1);        // n-chunk
    const int tid = threadIdx.x;
    const float* __restrict__ P = points + b * 3 * NPTS;

    // ---- per-block quaternion math: A = Rp^T * Rg for this batch ----
    if (tid == 0) {
        float p[4], g[4];
#pragma unroll
        for (int i = 0; i < 4; i++) { p[i] = pq[b * 4 + i]; g[i] = gq[b * 4 + i]; }
        float np2 = 0.f, ng2 = 0.f;
#pragma unroll
        for (int i = 0; i < 4; i++) { np2 += p[i] * p[i]; ng2 += g[i] * g[i]; }
        float ip = 1.f / fmaxf(sqrtf(np2), 1e-8f);
        float ig = 1.f / fmaxf(sqrtf(ng2), 1e-8f);
#pragma unroll
        for (int i = 0; i < 4; i++) { p[i] *= ip; g[i] *= ig; }
        float Rp[3][3], Rg[3][3];
        quat2mat(p, Rp);
        quat2mat(g, Rg);
#pragma unroll
        for (int i = 0; i < 3; i++)
#pragma unroll
            for (int j = 0; j < 3; j++) {
                float a = 0.f;
#pragma unroll
                for (int k = 0; k < 3; k++) a += Rp[k][i] * Rg[k][j];
                sA[i * 3 + j] = a;
            }
    }

    // ---- cos_loss: block 0, warp 0 (lanes 0..15 own one batch each) ----
    if (blockIdx.x == 0 && tid < 32) {
        float cos_term = 0.f;
        if (tid < NB) {
            float p[4], g[4];
#pragma unroll
            for (int i = 0; i < 4; i++) { p[i] = pq[tid * 4 + i]; g[i] = gq[tid * 4 + i]; }
            float dot = 0.f, np2 = 0.f, ng2 = 0.f;
#pragma unroll
            for (int i = 0; i < 4; i++) {
                dot += p[i] * g[i]; np2 += p[i] * p[i]; ng2 += g[i] * g[i];
            }
            cos_term = 1.f - dot / fmaxf(sqrtf(np2) * sqrtf(ng2), 1e-8f);
        }
#pragma unroll
        for (int o = 16; o > 0; o >>= 1) cos_term += __shfl_down_sync(0xFFFFFFFFu, cos_term, o);
        if (tid == 0) out[0] = cos_term * (1.f / (float)NB);
    }
    __syncthreads();

    const float A00 = sA[0], A01 = sA[1], A02 = sA[2];
    const float A10 = sA[3], A11 = sA[4], A12 = sA[5];
    const float A20 = sA[6], A21 = sA[7], A22 = sA[8];

    // ---- Phase 1: r/s table for this block's 64 n-points + chunk s-sum ----
    if (tid < NLOC) {
        int n = nc * NLOC + tid;
        float x = P[n], y = P[NPTS + n], z = P[2 * NPTS + n];
        float r0 = fmaf(A00, x, fmaf(A01, y, A02 * z));
        float r1 = fmaf(A10, x, fmaf(A11, y, A12 * z));
        float r2 = fmaf(A20, x, fmaf(A21, y, A22 * z));
        float s  = fmaf(x, x, fmaf(y, y, z * z));
        smN[tid] = make_float4(r0, r1, r2, s);

        float t = s;
#pragma unroll
        for (int o = 16; o > 0; o >>= 1) t += __shfl_down_sync(0xFFFFFFFFu, t, o);
        if ((tid & 31) == 0) red[tid >> 5] = t;
    }
    __syncthreads();
    if (tid == 0) {
        float t = 0.f;
#pragma unroll
        for (int w = 0; w < NLOC / 32; w++) t += red[w];
        g_ssum[blockIdx.x] = t;
    }

    // ---- Phase 2: each thread owns m = k*512 + tid, k in [0,4) ----
    float u0[MB], u1[MB], u2[MB];
#pragma unroll
    for (int k = 0; k < MB; k++) {
        int m = k * TPB + tid;
        u0[k] = -2.f * P[m];
        u1[k] = -2.f * P[NPTS + m];
        u2[k] = -2.f * P[2 * NPTS + m];
    }

    float mn[MB];
#pragma unroll
    for (int k = 0; k < MB; k++) mn[k] = INFINITY;

#pragma unroll 8
    for (int j = 0; j < NLOC; j++) {
        float4 t = smN[j];   // broadcast LDS.128: (r0, r1, r2, s)
#pragma unroll
        for (int k = 0; k < MB; k++) {
            float v = fmaf(u2[k], t.z, t.w);   // s - 2*r2*z
            v = fmaf(u1[k], t.y, v);           //   - 2*r1*y
            v = fmaf(u0[k], t.x, v);           //   - 2*r0*x
            mn[k] = fminf(mn[k], v);
        }
    }

#pragma unroll
    for (int k = 0; k < MB; k++) {
        // min over floats == max over reversed keys; identity 0 == untouched slot
        atomicMax(&g_min[b * NPTS + k * TPB + tid], fencMax(mn[k]));
    }

    // ---- hierarchical finish: per-batch last block reduces its batch ----
    __threadfence();
    if (tid == 0) {
        unsigned prev = atomicAdd(&g_cnt_b[b], 1u);
        isBatchLast = (prev == NCHUNK - 1);
    }
    __syncthreads();
    if (!isBatchLast) return;

    __threadfence();  // all chunks of batch b are visible

    // 512 threads x 1 uint4 = 2048 mins of this batch; read, decode, re-arm.
    {
        uint4* gm = (uint4*)(g_min + b * NPTS);
        uint4 v = gm[tid];
        float acc = fdecMax(v.x) + fdecMax(v.y) + fdecMax(v.z) + fdecMax(v.w);
        gm[tid] = make_uint4(0u, 0u, 0u, 0u);
        if (tid < NCHUNK) acc += g_ssum[b * NCHUNK + tid];

#pragma unroll
        for (int o = 16; o > 0; o >>= 1) acc += __shfl_down_sync(0xFFFFFFFFu, acc, o);
        if ((tid & 31) == 0) red[tid >> 5] = acc;
        __syncthreads();
        if (tid < 32) {
            acc = (tid < (TPB / 32)) ? red[tid] : 0.f;
#pragma unroll
            for (int o = 16; o > 0; o >>= 1) acc += __shfl_down_sync(0xFFFFFFFFu, acc, o);
            if (tid == 0) {
                g_bsum[b] = acc;
                g_cnt_b[b] = 0;              // re-arm per-batch counter
            }
        }
    }

    // ---- final: last batch-finisher sums the 16 batch totals ----
    __threadfence();
    if (tid == 0) {
        unsigned prev = atomicAdd(&g_count, 1u);
        isFinal = (prev == NB - 1);
    }
    __syncthreads();
    if (!isFinal) return;

    __threadfence();  // all g_bsum visible
    if (tid == 0) {
        float s = 0.f;
#pragma unroll
        for (int i = 0; i < NB; i++) s += g_bsum[i];   // fixed order -> deterministic
        float pt = s * (1.f / ((float)NB * (float)NPTS));
        if (isnan(pt)) pt = 0.f;
        out[1] = pt;
        g_count = 0;                        // re-arm final counter
    }
}

extern "C" void kernel_launch(void* const* d_in, const int* in_sizes, int n_in,
                              void* d_out, int out_size) {
    const float* pq  = (const float*)d_in[0];  // predquat (16,4)
    const float* gq  = (const float*)d_in[1];  // gtquat   (16,4)
    const float* pts = (const float*)d_in[2];  // points   (16,3,2048)
    float* out = (float*)d_out;                // [cos_loss, pt_loss]

    fused_kernel<<<NBLK, TPB>>>(pq, gq, pts, out);
}

// round 17
// speedup vs baseline: 1.1099x; 1.0137x over previous
#include <cuda_runtime.h>
#include <math.h>

#define NPTS   2048
#define NB     16
#define NCHUNK 16         // n-dimension split per batch
#define TPB    512
#define MB     4          // m-points per thread (TPB*MB = NPTS)
#define NLOC   (NPTS / NCHUNK)          // 128 n-points per block
#define NBLK   (NB * NCHUNK)            // 256 blocks
#define NSUM   (NB * NCHUNK)            // 256 s-sum slots

// All zero-initialized at module load; every replay leaves them re-armed to 0.
__device__ unsigned g_min[NB * NPTS];   // per-(b,m) running min, order-REVERSED keys
__device__ float    g_ssum[NSUM];       // per-(b,nc) partial sums of |p|^2
__device__ float    g_bsum[NB];         // per-batch totals (min + ssum)
__device__ unsigned g_cnt_b[NB];        // per-batch arrival counters
__device__ unsigned g_count = 0;        // final arrival counter

// ---- order-REVERSING float<->uint keys: min(float) == max(key), identity = 0 ----
__device__ __forceinline__ unsigned fencMax(float f) {
    unsigned u = __float_as_uint(f);
    return (u & 0x80000000u) ? u : (~u & 0x7FFFFFFFu);
}
__device__ __forceinline__ float fdecMax(unsigned k) {
    unsigned u = (k & 0x80000000u) ? k : (~k & 0x7FFFFFFFu);
    return __uint_as_float(u);
}

__device__ __forceinline__ void quat2mat(const float q[4], float R[3][3]) {
    float w = q[0], x = q[1], y = q[2], z = q[3];
    R[0][0] = 1.f - 2.f * (y * y + z * z);
    R[0][1] = 2.f * (x * y - w * z);
    R[0][2] = 2.f * (x * z + w * y);
    R[1][0] = 2.f * (x * y + w * z);
    R[1][1] = 1.f - 2.f * (x * x + z * z);
    R[1][2] = 2.f * (y * z - w * x);
    R[2][0] = 2.f * (x * z - w * y);
    R[2][1] = 2.f * (y * z + w * x);
    R[2][2] = 1.f - 2.f * (x * x + y * y);
}

// Single fused kernel. grid = 16 batches x 16 n-chunks, 512 threads.
__global__ __launch_bounds__(TPB, 2) void fused_kernel(const float* __restrict__ pq,
                                                       const float* __restrict__ gq,
                                                       const float* __restrict__ points,
                                                       float* __restrict__ out) {
    __shared__ float4 smN[NLOC];        // (r0, r1, r2, s) per n-point
    __shared__ float  sA[9];
    __shared__ float  red[TPB / 32];
    __shared__ bool   isBatchLast, isFinal;

    const int b   = blockIdx.x >> 4;                  // batch
    const int nc  = blockIdx.x & (NCHUNK - 1);        // n-chunk
    const int tid = threadIdx.x;
    const float* __restrict__ P = points + b * 3 * NPTS;

    // ---- per-block quaternion math: A = Rp^T * Rg for this batch ----
    if (tid == 0) {
        float p[4], g[4];
#pragma unroll
        for (int i = 0; i < 4; i++) { p[i] = pq[b * 4 + i]; g[i] = gq[b * 4 + i]; }
        float np2 = 0.f, ng2 = 0.f;
#pragma unroll
        for (int i = 0; i < 4; i++) { np2 += p[i] * p[i]; ng2 += g[i] * g[i]; }
        float ip = 1.f / fmaxf(sqrtf(np2), 1e-8f);
        float ig = 1.f / fmaxf(sqrtf(ng2), 1e-8f);
#pragma unroll
        for (int i = 0; i < 4; i++) { p[i] *= ip; g[i] *= ig; }
        float Rp[3][3], Rg[3][3];
        quat2mat(p, Rp);
        quat2mat(g, Rg);
#pragma unroll
        for (int i = 0; i < 3; i++)
#pragma unroll
            for (int j = 0; j < 3; j++) {
                float a = 0.f;
#pragma unroll
                for (int k = 0; k < 3; k++) a += Rp[k][i] * Rg[k][j];
                sA[i * 3 + j] = a;
            }
    }

    // ---- cos_loss: block 0, warp 0 (lanes 0..15 own one batch each) ----
    if (blockIdx.x == 0 && tid < 32) {
        float cos_term = 0.f;
        if (tid < NB) {
            float p[4], g[4];
#pragma unroll
            for (int i = 0; i < 4; i++) { p[i] = pq[tid * 4 + i]; g[i] = gq[tid * 4 + i]; }
            float dot = 0.f, np2 = 0.f, ng2 = 0.f;
#pragma unroll
            for (int i = 0; i < 4; i++) {
                dot += p[i] * g[i]; np2 += p[i] * p[i]; ng2 += g[i] * g[i];
            }
            cos_term = 1.f - dot / fmaxf(sqrtf(np2) * sqrtf(ng2), 1e-8f);
        }
#pragma unroll
        for (int o = 16; o > 0; o >>= 1) cos_term += __shfl_down_sync(0xFFFFFFFFu, cos_term, o);
        if (tid == 0) out[0] = cos_term * (1.f / (float)NB);
    }
    __syncthreads();

    const float A00 = sA[0], A01 = sA[1], A02 = sA[2];
    const float A10 = sA[3], A11 = sA[4], A12 = sA[5];
    const float A20 = sA[6], A21 = sA[7], A22 = sA[8];

    // ---- Phase 1: r/s table for this block's 128 n-points + chunk s-sum ----
    if (tid < NLOC) {
        int n = nc * NLOC + tid;
        float x = P[n], y = P[NPTS + n], z = P[2 * NPTS + n];
        float r0 = fmaf(A00, x, fmaf(A01, y, A02 * z));
        float r1 = fmaf(A10, x, fmaf(A11, y, A12 * z));
        float r2 = fmaf(A20, x, fmaf(A21, y, A22 * z));
        float s  = fmaf(x, x, fmaf(y, y, z * z));
        smN[tid] = make_float4(r0, r1, r2, s);

        float t = s;
#pragma unroll
        for (int o = 16; o > 0; o >>= 1) t += __shfl_down_sync(0xFFFFFFFFu, t, o);
        if ((tid & 31) == 0) red[tid >> 5] = t;
    }
    __syncthreads();
    if (tid == 0) {
        float t = 0.f;
#pragma unroll
        for (int w = 0; w < NLOC / 32; w++) t += red[w];
        g_ssum[blockIdx.x] = t;
    }

    // ---- Phase 2: each thread owns m = k*512 + tid, k in [0,4) ----
    float u0[MB], u1[MB], u2[MB];
#pragma unroll
    for (int k = 0; k < MB; k++) {
        int m = k * TPB + tid;
        u0[k] = -2.f * P[m];
        u1[k] = -2.f * P[NPTS + m];
        u2[k] = -2.f * P[2 * NPTS + m];
    }

    float mn[MB];
#pragma unroll
    for (int k = 0; k < MB; k++) mn[k] = INFINITY;

    // Warp-staggered scan: warp w starts at offset w*8 so the 16 warps issue
    // their broadcast LDS.128s against different table entries each cycle,
    // decorrelating MIO bursts. Two unrolled sub-loops avoid wrap arithmetic.
    const int woff = (tid >> 5) << 3;   // warp * 8, in [0, 120]
#pragma unroll 8
    for (int j = woff; j < NLOC; j++) {
        float4 t = smN[j];
#pragma unroll
        for (int k = 0; k < MB; k++) {
            float v = fmaf(u2[k], t.z, t.w);   // s - 2*r2*z
            v = fmaf(u1[k], t.y, v);           //   - 2*r1*y
            v = fmaf(u0[k], t.x, v);           //   - 2*r0*x
            mn[k] = fminf(mn[k], v);
        }
    }
#pragma unroll 8
    for (int j = 0; j < woff; j++) {
        float4 t = smN[j];
#pragma unroll
        for (int k = 0; k < MB; k++) {
            float v = fmaf(u2[k], t.z, t.w);
            v = fmaf(u1[k], t.y, v);
            v = fmaf(u0[k], t.x, v);
            mn[k] = fminf(mn[k], v);
        }
    }

#pragma unroll
    for (int k = 0; k < MB; k++) {
        // min over floats == max over reversed keys; identity 0 == untouched slot
        atomicMax(&g_min[b * NPTS + k * TPB + tid], fencMax(mn[k]));
    }

    // ---- hierarchical finish: per-batch last block reduces its batch ----
    __threadfence();
    if (tid == 0) {
        unsigned prev = atomicAdd(&g_cnt_b[b], 1u);
        isBatchLast = (prev == NCHUNK - 1);
    }
    __syncthreads();
    if (!isBatchLast) return;

    __threadfence();  // all chunks of batch b are visible

    // 512 threads x 1 uint4 = 2048 mins of this batch; read, decode, re-arm.
    {
        uint4* gm = (uint4*)(g_min + b * NPTS);
        uint4 v = gm[tid];
        float acc = fdecMax(v.x) + fdecMax(v.y) + fdecMax(v.z) + fdecMax(v.w);
        gm[tid] = make_uint4(0u, 0u, 0u, 0u);
        if (tid < NCHUNK) acc += g_ssum[b * NCHUNK + tid];

#pragma unroll
        for (int o = 16; o > 0; o >>= 1) acc += __shfl_down_sync(0xFFFFFFFFu, acc, o);
        if ((tid & 31) == 0) red[tid >> 5] = acc;
        __syncthreads();
        if (tid < 32) {
            acc = (tid < (TPB / 32)) ? red[tid] : 0.f;
#pragma unroll
            for (int o = 16; o > 0; o >>= 1) acc += __shfl_down_sync(0xFFFFFFFFu, acc, o);
            if (tid == 0) {
                g_bsum[b] = acc;
                g_cnt_b[b] = 0;              // re-arm per-batch counter
            }
        }
    }

    // ---- final: last batch-finisher sums the 16 batch totals ----
    __threadfence();
    if (tid == 0) {
        unsigned prev = atomicAdd(&g_count, 1u);
        isFinal = (prev == NB - 1);
    }
    __syncthreads();
    if (!isFinal) return;

    __threadfence();  // all g_bsum visible
    if (tid == 0) {
        float s = 0.f;
#pragma unroll
        for (int i = 0; i < NB; i++) s += g_bsum[i];   // fixed order -> deterministic
        float pt = s * (1.f / ((float)NB * (float)NPTS));
        if (isnan(pt)) pt = 0.f;
        out[1] = pt;
        g_count = 0;                        // re-arm final counter
    }
}

extern "C" void kernel_launch(void* const* d_in, const int* in_sizes, int n_in,
                              void* d_out, int out_size) {
    const float* pq  = (const float*)d_in[0];  // predquat (16,4)
    const float* gq  = (const float*)d_in[1];  // gtquat   (16,4)
    const float* pts = (const float*)d_in[2];  // points   (16,3,2048)
    float* out = (float*)d_out;                // [cos_loss, pt_loss]

    fused_kernel<<<NBLK, TPB>>>(pq, gq, pts, out);
}